// round 15
// baseline (speedup 1.0000x reference)
#include <cuda_runtime.h>
#include <cstdint>

// Temporal_Attention — weight-space-collapsed, batch-amortized weights.
//  K1 k_pre : xs[b], M = Wv_h@Wo_h, cbias partials, S.      (PDL trigger@entry)
//  K2 k_u   : per (head, batch-quad): Khat = xs@Wk_h + S*bk; U = scale*Khat@Wq_h^T;
//             c = scale*Khat.bq_h + bs.   Weights read ONCE. (PDL: weight loads
//             overlap K1; gridDepSync before xs use)
//  K3 k_attn: per (batch, head-half): fill x, summary, softmax, y -> gmem.
//             No clusters, no G/M streams.  (PDL: fill overlaps K2)
//  K4 k_out : per (batch-oct, 16-col tile): out = Y@M + cbias.
// B=64, T=256, D=128, H=8, E=128.  out[B,D] fp32.

#define BB 64
#define TT 256
#define DD 128
#define HH 8
#define HE 1024
#define SCALE 0.088388347648318447f

static __device__ float g_S;
static __device__ __align__(16) float g_xs[BB * DD];
static __device__ __align__(16) float g_M[HE * DD];        // [k][d2]
static __device__ __align__(16) float g_cbp[8 * DD];
static __device__ __align__(16) float g_U[BB * HE];        // [b][h*128+d]
static __device__ float g_c[BB * HH];
static __device__ __align__(16) float g_Y[BB * HE];        // [b][h*128+d]

// ---- helpers ---------------------------------------------------------------
__device__ __forceinline__ void ffma2(unsigned long long& d,
                                      unsigned long long a, unsigned long long b) {
    asm("fma.rn.f32x2 %0, %1, %2, %0;" : "+l"(d) : "l"(a), "l"(b));
}
__device__ __forceinline__ unsigned long long pk2(float x, float y) {
    unsigned long long r;
    asm("mov.b64 %0, {%1, %2};" : "=l"(r) : "f"(x), "f"(y));
    return r;
}
__device__ __forceinline__ float2 upk2(unsigned long long v) {
    float lo, hi;
    asm("mov.b64 {%0, %1}, %2;" : "=f"(lo), "=f"(hi) : "l"(v));
    return make_float2(lo, hi);
}
__device__ __forceinline__ float dot4(float4 a, float4 b) {
    return a.x * b.x + a.y * b.y + a.z * b.z + a.w * b.w;
}

// ===========================================================================
// K1: grid 201 x 256. roles: xs(0-63) | M(64-191, 8-row tiles) | cbias(192-199)
//                            | S(200)
__global__ __launch_bounds__(256) void k_pre(
    const float* __restrict__ x,  const float* __restrict__ Ws,
    const float* __restrict__ Wv, const float* __restrict__ bv,
    const float* __restrict__ Wo, const float* __restrict__ bo)
{
    cudaTriggerProgrammaticLaunchCompletion();

    __shared__ __align__(16) float s[8704];   // 34 KB
    const int blk = blockIdx.x, tid = threadIdx.x;

    if (blk < 64) {
        // ------------- xs role: one batch -------------
        const int b = blk, c = tid & 31, tg = tid >> 5;
        const float4* x4 = (const float4*)x;
        float4 acc = make_float4(0.f, 0.f, 0.f, 0.f);
        #pragma unroll 16
        for (int t = tg * 32; t < tg * 32 + 32; t++) {
            float w = __ldg(Ws + t);
            float4 xv = x4[(b * TT + t) * 32 + c];
            acc.x += w * xv.x; acc.y += w * xv.y;
            acc.z += w * xv.z; acc.w += w * xv.w;
        }
        float4* p4 = (float4*)s;
        p4[tg * 32 + c] = acc;
        __syncthreads();
        if (tid < 32) {
            float4 r = p4[tid];
            #pragma unroll
            for (int g = 1; g < 8; g++) {
                float4 v = p4[g * 32 + tid];
                r.x += v.x; r.y += v.y; r.z += v.z; r.w += v.w;
            }
            ((float4*)g_xs)[b * 32 + tid] = r;
        }
    } else if (blk < 192) {
        // ------------- M role: M[h, r0..r0+7, :] -------------
        const int w = blk - 64, h = w >> 4, r0 = (w & 15) * 8;
        const int d2 = tid & 127, rh = tid >> 7;   // 2 groups of 4 rows
        float* wo_s = s;            // 64 x 128 = 8192
        float* wv_s = s + 8192;     // 8 x 64 = 512
        float acc[4];
        #pragma unroll
        for (int j = 0; j < 4; j++) acc[j] = 0.f;
        for (int e0 = 0; e0 < 128; e0 += 64) {
            for (int i = tid; i < 8192; i += 256) {
                int e = i >> 7, dd = i & 127;
                wo_s[i] = Wo[(h * 128 + e0 + e) * DD + dd];
            }
            for (int i = tid; i < 512; i += 256) {   // FIX: strided, 256 thr
                int r = i >> 6, e = i & 63;
                wv_s[i] = Wv[(r0 + r) * HE + h * 128 + e0 + e];
            }
            __syncthreads();
            #pragma unroll 8
            for (int e = 0; e < 64; e++) {
                float wo = wo_s[e * 128 + d2];
                #pragma unroll
                for (int j = 0; j < 4; j++)
                    acc[j] += wv_s[(rh * 4 + j) * 64 + e] * wo;
            }
            __syncthreads();
        }
        #pragma unroll
        for (int j = 0; j < 4; j++)
            g_M[(h * 128 + r0 + rh * 4 + j) * DD + d2] = acc[j];
    } else if (blk < 200) {
        // ------------- cbias partial: k-slice p -------------
        const int p = blk - 192, d2 = tid & 127, kh = tid >> 7;
        float acc = 0.f;
        #pragma unroll 8
        for (int i = 0; i < 64; i++) {
            int k = p * 128 + kh * 64 + i;
            acc += __ldg(bv + k) * Wo[k * DD + d2];
        }
        s[tid] = acc;
        __syncthreads();
        if (kh == 0)
            g_cbp[p * DD + d2] = s[d2] + s[128 + d2] + (p == 0 ? bo[d2] : 0.f);
    } else {
        // ------------- S -------------
        s[tid] = Ws[tid];
        __syncthreads();
        for (int st = 128; st > 0; st >>= 1) {
            if (tid < st) s[tid] += s[tid + st];
            __syncthreads();
        }
        if (tid == 0) g_S = s[0];
    }
}

// ===========================================================================
// K2: grid 128 = (h = blk>>4, quad = blk&15).  256 thr, dyn smem ~138 KB.
//   Khat[4b,128e] = xs@Wk_h + S*bk_h ; U = scale*Khat@Wq_h^T ; c = scale*Khat.bq_h+bs
#define U_WK   0        // wk_s [128 d][128 e]          16384
#define U_WQT  16384    // wq_t [128 e][133 pad] (e-major) 17024
#define U_XS   33408    // xs 4x128                     512
#define U_KH   33920    // kh 4x128                     512
#define U_FLOATS 34432

extern "C" __global__ __launch_bounds__(256, 1)
void k_u(const float* __restrict__ Wk, const float* __restrict__ bk,
         const float* __restrict__ Wq, const float* __restrict__ bq,
         const float* __restrict__ bs)
{
    extern __shared__ __align__(16) float smu[];
    float* wk_s = smu + U_WK;
    float* wq_t = smu + U_WQT;
    float* xs_s = smu + U_XS;
    float* kh_s = smu + U_KH;

    const int tid = threadIdx.x;
    const int h = blockIdx.x >> 4, quad = blockIdx.x & 15;
    const int b0 = quad * 4;

    cudaTriggerProgrammaticLaunchCompletion();   // let K3 launch early

    // ---- load weights (independent of K1; overlaps it under PDL) ----
    {
        float4* wk4 = (float4*)wk_s;
        const float4* Wk4 = (const float4*)Wk;
        #pragma unroll
        for (int k = 0; k < 16; k++) {
            int i4 = tid + k * 256;
            int d = i4 >> 5, e4 = i4 & 31;
            wk4[d * 32 + e4] = Wk4[d * 256 + h * 32 + e4];
        }
        #pragma unroll
        for (int k = 0; k < 64; k++) {
            int i = tid + k * 256;
            int d = i >> 7, e = i & 127;
            wq_t[e * 133 + d] = Wq[d * HE + h * 128 + e];
        }
    }

    // need xs and S from K1 now
    cudaGridDependencySynchronize();
    xs_s[tid]       = g_xs[b0 * DD + tid];          // FIX: both halves, 256 thr
    xs_s[tid + 256] = g_xs[b0 * DD + tid + 256];
    __syncthreads();
    const float S = g_S;

    // ---- Khat: thread (e = tid&127, bb = tid>>7): batches 2bb, 2bb+1 ----
    {
        const int e = tid & 127, bb = tid >> 7;
        const int bl0 = bb * 2, bl1 = bb * 2 + 1;
        float base = S * __ldg(bk + h * 128 + e);
        float a0 = base, a1 = base;
        const float* x0 = xs_s + bl0 * 128;
        const float* x1 = xs_s + bl1 * 128;
        #pragma unroll 8
        for (int d = 0; d < 128; d++) {
            float wv = wk_s[d * 128 + e];
            a0 += x0[d] * wv;
            a1 += x1[d] * wv;
        }
        kh_s[bl0 * 128 + e] = a0;
        kh_s[bl1 * 128 + e] = a1;
    }
    __syncthreads();

    // ---- U: thread (d = tid&127, bb): u[b,h,d] = scale * kh.wq_t[:,d] ----
    {
        const int d = tid & 127, bb = tid >> 7;
        const int bl0 = bb * 2, bl1 = bb * 2 + 1;
        float a0 = 0.f, a1 = 0.f;
        const float* k0 = kh_s + bl0 * 128;
        const float* k1 = kh_s + bl1 * 128;
        #pragma unroll 8
        for (int e = 0; e < 128; e++) {
            float wv = wq_t[e * 133 + d];
            a0 += k0[e] * wv;
            a1 += k1[e] * wv;
        }
        g_U[(b0 + bl0) * HE + h * 128 + d] = SCALE * a0;
        g_U[(b0 + bl1) * HE + h * 128 + d] = SCALE * a1;
    }

    // ---- c: warp w (<4) handles batch b0+w ----
    if (tid < 128) {
        int bl = tid >> 5, lane = tid & 31;
        float p = dot4(((const float4*)kh_s)[bl * 32 + lane],
                       ((const float4*)bq)[h * 32 + lane]);
        #pragma unroll
        for (int o = 16; o > 0; o >>= 1)
            p += __shfl_xor_sync(0xffffffffu, p, o);
        if (lane == 0) g_c[(b0 + bl) * 8 + h] = SCALE * p + bs[0];
    }
}

// ===========================================================================
// K3: grid 128 = (b = blk>>1, r = blk&1 -> heads 4r..4r+3).  1024 thr.
//   fill x, summary, softmax, y -> g_Y.  No clusters.
#define SX_PAD  132
#define OSX   0        // sx [256 t][132 pad]   33792
#define OSU   33792    // su [128 d][4 h] / sy  512
#define OSC   34304    // c[4] (pad to 8)       8
#define OSCO  34312    // scores [4 h][256 t]   1024
#define OBT   35336    // beta [256 t][4 h]     1024
#define OPART 36360    // scratch               4096
#define K3_FLOATS 40456

extern "C" __global__ __launch_bounds__(1024, 1)
void k_attn(const float* __restrict__ x)
{
    extern __shared__ __align__(16) float sm[];
    float* sx    = sm + OSX;
    float* su    = sm + OSU;     // u, later reused as sy
    float* sc    = sm + OSC;
    float* sco   = sm + OSCO;
    float* sbeta = sm + OBT;
    float* spart = sm + OPART;

    const int tid = threadIdx.x;
    const int b = blockIdx.x >> 1, r = blockIdx.x & 1;

    // ---- fill x tile [t][d] (overlaps K2 under PDL) ----
    {
        const int d = tid & 127, tg = tid >> 7;   // 8 t-groups of 32
        const float* xb = x + ((size_t)b * TT) * DD + d;
        #pragma unroll
        for (int k = 0; k < 32; k++) {
            int t = k * 8 + tg;
            sx[t * SX_PAD + d] = xb[t * DD];
        }
    }

    // need U, c from K2
    cudaGridDependencySynchronize();
    if (tid < 512) {
        int h_l = tid >> 7, d = tid & 127;
        su[d * 4 + h_l] = g_U[b * HE + (4 * r + h_l) * 128 + d];
    } else if (tid < 516) {
        sc[tid - 512] = g_c[b * 8 + 4 * r + (tid - 512)];
    }
    __syncthreads();

    // ---- summary for own 4 heads; thread (t = tid&255, dq = tid>>8 of 4) ----
    {
        const int t = tid & 255, dq = tid >> 8;
        float xr[32];
        const float4* xrow = (const float4*)(sx + t * SX_PAD + dq * 32);
        #pragma unroll
        for (int i = 0; i < 8; i++) {
            float4 v = xrow[i];
            xr[i * 4 + 0] = v.x; xr[i * 4 + 1] = v.y;
            xr[i * 4 + 2] = v.z; xr[i * 4 + 3] = v.w;
        }
        unsigned long long a0 = 0, a1 = 0;
        #pragma unroll
        for (int i = 0; i < 32; i++) {
            int d = dq * 32 + i;
            unsigned long long xp = pk2(xr[i], xr[i]);
            ulonglong2 u4 = *(const ulonglong2*)(su + d * 4);
            ffma2(a0, u4.x, xp);
            ffma2(a1, u4.y, xp);
        }
        float2 f0 = upk2(a0), f1 = upk2(a1);
        float* pp = spart + dq * 1024 + t;
        pp[0]   = f0.x; pp[256] = f0.y;
        pp[512] = f1.x; pp[768] = f1.y;
    }
    __syncthreads();
    {   // reduce dq -> sco[h_l*256 + t]
        int h_l = tid >> 8, t = tid & 255;
        const float* pp = spart + h_l * 256 + t;
        sco[tid] = pp[0] + pp[1024] + pp[2048] + pp[3072] + sc[h_l];
    }
    __syncthreads();

    // ---- full softmax over t (warp per own head) ----
    if (tid < 128) {
        int h_l = tid >> 5, lane = tid & 31;
        float v[8];
        float m = -1e30f;
        #pragma unroll
        for (int i = 0; i < 8; i++) {
            v[i] = sco[h_l * 256 + lane + 32 * i];
            m = fmaxf(m, v[i]);
        }
        #pragma unroll
        for (int o = 16; o > 0; o >>= 1)
            m = fmaxf(m, __shfl_xor_sync(0xffffffffu, m, o));
        float ss = 0.f;
        #pragma unroll
        for (int i = 0; i < 8; i++) { v[i] = __expf(v[i] - m); ss += v[i]; }
        #pragma unroll
        for (int o = 16; o > 0; o >>= 1)
            ss += __shfl_xor_sync(0xffffffffu, ss, o);
        float inv = 1.f / ss;
        #pragma unroll
        for (int i = 0; i < 8; i++)
            sbeta[(lane + 32 * i) * 4 + h_l] = v[i] * inv;
    }
    __syncthreads();

    // ---- y for own heads; thread (d = tid&127, tg = tid>>7 of 8) ----
    {
        const int d = tid & 127, tg = tid >> 7;
        unsigned long long a0 = 0, a1 = 0;
        #pragma unroll
        for (int i = 0; i < 32; i++) {
            int t = tg * 32 + i;
            float xv = sx[t * SX_PAD + d];
            unsigned long long xp = pk2(xv, xv);
            ulonglong2 b4 = *(const ulonglong2*)(sbeta + t * 4);
            ffma2(a0, b4.x, xp);
            ffma2(a1, b4.y, xp);
        }
        float2 v0 = upk2(a0), v1 = upk2(a1);
        float* pg = spart + tg * 512;
        pg[0 * 128 + d] = v0.x; pg[1 * 128 + d] = v0.y;
        pg[2 * 128 + d] = v1.x; pg[3 * 128 + d] = v1.y;
    }
    __syncthreads();
    if (tid < 512) {   // reduce 8 t-groups; write y slice (k = r*512 + tid)
        float v = 0.f;
        #pragma unroll
        for (int g = 0; g < 8; g++) v += spart[g * 512 + tid];
        g_Y[b * HE + r * 512 + tid] = v;
    }
}

// ===========================================================================
// K4: grid 64 = (oct = blk>>3, dq = blk&7 -> 16 cols).  256 thr.
//   out[8b, 16 cols] = Y[8b,1024] @ M[:, cols] + cbias
__global__ __launch_bounds__(256) void k_out(float* __restrict__ out)
{
    __shared__ __align__(16) float y_s[8 * HE];     // 32 KB
    __shared__ __align__(16) float part[1024];      // 4 KB
    __shared__ float cb_s[16];
    const int oct = blockIdx.x >> 3, dq = blockIdx.x & 7;
    const int b0 = oct * 8;
    const int tid = threadIdx.x;

    cudaGridDependencySynchronize();   // Y from K3, M/cbp from K1 (transitive)

    {
        float4* y4 = (float4*)y_s;
        const float4* gY4 = (const float4*)(g_Y + (size_t)b0 * HE);
        #pragma unroll
        for (int k = 0; k < 8; k++) y4[tid + k * 256] = gY4[tid + k * 256];
    }
    if (tid < 16) {
        float cb = 0.f;
        #pragma unroll
        for (int p = 0; p < 8; p++) cb += g_cbp[p * DD + dq * 16 + tid];
        cb_s[tid] = cb;
    }
    __syncthreads();

    {   // thread (f4 = tid&3, bb = (tid>>2)&7, kg = tid>>5 of 8 x 128 k)
        const int f4 = tid & 3, bb = (tid >> 2) & 7, kg = tid >> 5;
        const float4* M4 = (const float4*)g_M + dq * 4 + f4;
        const float* yr = y_s + bb * HE;
        float4 acc = make_float4(0.f, 0.f, 0.f, 0.f);
        #pragma unroll 8
        for (int kk = 0; kk < 128; kk++) {
            int k = kg * 128 + kk;
            float yk = yr[k];
            float4 mv = M4[k * 32];
            acc.x += yk * mv.x; acc.y += yk * mv.y;
            acc.z += yk * mv.z; acc.w += yk * mv.w;
        }
        ((float4*)part)[(kg * 8 + bb) * 4 + f4] = acc;
    }
    __syncthreads();
    if (tid < 128) {
        int bb = tid >> 4, cf = tid & 15;
        float o = cb_s[cf];
        #pragma unroll
        for (int kg = 0; kg < 8; kg++) o += part[(kg * 8 + bb) * 16 + cf];
        out[(b0 + bb) * DD + dq * 16 + cf] = o;
    }
}

// ===========================================================================
extern "C" void kernel_launch(void* const* d_in, const int* in_sizes, int n_in,
                              void* d_out, int out_size) {
    const float* x  = (const float*)d_in[0];
    const float* Wq = (const float*)d_in[1];
    const float* bq = (const float*)d_in[2];
    const float* Wk = (const float*)d_in[3];
    const float* bk = (const float*)d_in[4];
    const float* Wv = (const float*)d_in[5];
    const float* bv = (const float*)d_in[6];
    const float* Ws = (const float*)d_in[7];
    const float* bs = (const float*)d_in[8];
    const float* Wo = (const float*)d_in[9];
    const float* bo = (const float*)d_in[10];
    float* out = (float*)d_out;

    static bool attr_done = false;
    if (!attr_done) {
        cudaFuncSetAttribute(k_u, cudaFuncAttributeMaxDynamicSharedMemorySize,
                             U_FLOATS * 4);
        cudaFuncSetAttribute(k_attn, cudaFuncAttributeMaxDynamicSharedMemorySize,
                             K3_FLOATS * 4);
        attr_done = true;
    }

    cudaLaunchAttribute pdl[1];
    pdl[0].id = cudaLaunchAttributeProgrammaticStreamSerialization;
    pdl[0].val.programmaticStreamSerializationAllowed = 1;

    // K1: trigger at entry
    k_pre<<<201, 256>>>(x, Ws, Wv, bv, Wo, bo);

    // K2: PDL — weight loads overlap K1; gridDepSync before xs/S use
    {
        cudaLaunchConfig_t cfg = {};
        cfg.gridDim = dim3(128, 1, 1);
        cfg.blockDim = dim3(256, 1, 1);
        cfg.dynamicSmemBytes = U_FLOATS * 4;
        cfg.stream = 0;
        cfg.attrs = pdl;
        cfg.numAttrs = 1;
        cudaLaunchKernelEx(&cfg, k_u, Wk, bk, Wq, bq, bs);
    }

    // K3: PDL — x fill overlaps K2; gridDepSync before U/c use
    {
        cudaLaunchConfig_t cfg = {};
        cfg.gridDim = dim3(128, 1, 1);
        cfg.blockDim = dim3(1024, 1, 1);
        cfg.dynamicSmemBytes = K3_FLOATS * 4;
        cfg.stream = 0;
        cfg.attrs = pdl;
        cfg.numAttrs = 1;
        cudaLaunchKernelEx(&cfg, k_attn, x);
    }

    // K4: PDL (gridDepSync at top; needs Y from K3, M transitively)
    {
        cudaLaunchConfig_t cfg = {};
        cfg.gridDim = dim3(64, 1, 1);
        cfg.blockDim = dim3(256, 1, 1);
        cfg.dynamicSmemBytes = 0;
        cfg.stream = 0;
        cfg.attrs = pdl;
        cfg.numAttrs = 1;
        cudaLaunchKernelEx(&cfg, k_out, out);
    }
}

// round 16
// speedup vs baseline: 1.4556x; 1.4556x over previous
#include <cuda_runtime.h>
#include <cstdint>

// Temporal_Attention — weight-space-collapsed, head-split.
// Softmax shift-invariance: c[b,h] (const in t) dropped entirely.
// k_pre: G' = scale*Wk@Wq^T per head, ub' = scale*Wq@bk, M = Wv@Wo, cbias, S.
//        512 thr/block, grid 133 (one wave), PDL trigger at entry.
// k_main: 2 CTAs per batch (cluster 2), each owns 4 HEADS. grid 128 x 1024
//         thr, 1 CTA/SM. Softmax CTA-local; one DSMEM exchange at the end.
// B=64, T=256, D=128, H=8, E=128.  out[B,D] fp32.

#define BB 64
#define TT 256
#define DD 128
#define HH 8
#define HE 1024
#define SCALE 0.088388347648318447f

static __device__ float g_S;
static __device__ __align__(16) float g_G[HH * DD * DD];   // [h][dp][d]
static __device__ __align__(16) float g_ub[HH * DD];
static __device__ __align__(16) float g_M[HE * DD];        // [k][d2]
static __device__ __align__(16) float g_cbp[4 * DD];

// ---- helpers ---------------------------------------------------------------
__device__ __forceinline__ void ffma2(unsigned long long& d,
                                      unsigned long long a, unsigned long long b) {
    asm("fma.rn.f32x2 %0, %1, %2, %0;" : "+l"(d) : "l"(a), "l"(b));
}
__device__ __forceinline__ unsigned long long pk2(float x, float y) {
    unsigned long long r;
    asm("mov.b64 %0, {%1, %2};" : "=l"(r) : "f"(x), "f"(y));
    return r;
}
__device__ __forceinline__ float2 upk2(unsigned long long v) {
    float lo, hi;
    asm("mov.b64 {%0, %1}, %2;" : "=f"(lo), "=f"(hi) : "l"(v));
    return make_float2(lo, hi);
}
__device__ __forceinline__ float dot4(float4 a, float4 b) {
    return a.x * b.x + a.y * b.y + a.z * b.z + a.w * b.w;
}
__device__ __forceinline__ uint32_t smem_u32(const void* p) {
    uint32_t a;
    asm("{ .reg .u64 t; cvta.to.shared.u64 t, %1; cvt.u32.u64 %0, t; }"
        : "=r"(a) : "l"(p));
    return a;
}
__device__ __forceinline__ uint32_t mapa_rank(uint32_t addr, uint32_t rank) {
    uint32_t r;
    asm("mapa.shared::cluster.u32 %0, %1, %2;" : "=r"(r) : "r"(addr), "r"(rank));
    return r;
}
__device__ __forceinline__ float ld_dsmem(uint32_t a) {
    float v;
    asm volatile("ld.shared::cluster.f32 %0, [%1];" : "=f"(v) : "r"(a));
    return v;
}
#define CLUSTER_SYNC() do { \
    asm volatile("barrier.cluster.arrive.aligned;" ::: "memory"); \
    asm volatile("barrier.cluster.wait.aligned;" ::: "memory"); \
} while (0)

// ===========================================================================
// K1: grid 133 x 512.  roles: G(0-63) | M(64-127) | cbias(128-131) | S(132)
__global__ __launch_bounds__(512) void k_pre(
    const float* __restrict__ Ws,
    const float* __restrict__ Wk, const float* __restrict__ bk,
    const float* __restrict__ Wq,
    const float* __restrict__ Wv, const float* __restrict__ bv,
    const float* __restrict__ Wo, const float* __restrict__ bo)
{
    cudaTriggerProgrammaticLaunchCompletion();

    __shared__ __align__(16) float s[12288];   // 48 KB
    const int blk = blockIdx.x, tid = threadIdx.x;

    if (blk < 64) {
        // ---- G role: G'[h, r0..r0+15, :] (+ub on rt==0), 512 thr ----
        const int h = blk >> 3, rt = blk & 7, r0 = rt * 16;
        const int d2 = tid & 127, rg = tid >> 7;   // 4 row-groups of 4
        float4* wq4s = (float4*)s;            // [128][17] float4
        float4* wk4s = (float4*)(s + 8704);   // [16][16]
        float4* bk4s = (float4*)(s + 9728);   // [16]
        const float4* Wq4 = (const float4*)Wq;
        const float4* Wk4 = (const float4*)Wk;
        float acc[4];
        #pragma unroll
        for (int j = 0; j < 4; j++) acc[j] = 0.f;
        float ubacc = 0.f;
        for (int e0 = 0; e0 < 2; e0++) {           // e-chunks of 64
            #pragma unroll
            for (int k = 0; k < 4; k++) {
                int i = tid + k * 512;             // 2048 f4 entries
                int dd = i >> 4, eq = i & 15;
                wq4s[dd * 17 + eq] = Wq4[dd * 256 + h * 32 + e0 * 16 + eq];
            }
            if (tid < 256) {
                int r = tid >> 4, eq = tid & 15;
                wk4s[r * 16 + eq] = Wk4[(r0 + r) * 256 + h * 32 + e0 * 16 + eq];
            }
            if (rt == 0 && tid < 16)
                bk4s[tid] = ((const float4*)bk)[h * 32 + e0 * 16 + tid];
            __syncthreads();
            #pragma unroll 4
            for (int e4 = 0; e4 < 16; e4++) {
                float4 q4 = wq4s[d2 * 17 + e4];
                #pragma unroll
                for (int j = 0; j < 4; j++)
                    acc[j] += dot4(q4, wk4s[(rg * 4 + j) * 16 + e4]);
                if (rt == 0 && rg == 0) ubacc += dot4(q4, bk4s[e4]);
            }
            __syncthreads();
        }
        #pragma unroll
        for (int j = 0; j < 4; j++)
            g_G[h * 16384 + (r0 + rg * 4 + j) * DD + d2] = SCALE * acc[j];
        if (rt == 0 && rg == 0) g_ub[h * DD + d2] = SCALE * ubacc;
    } else if (blk < 128) {
        // ---- M role: M[h, r0..r0+15, :], 512 thr ----
        const int w = blk - 64, h = w >> 3, r0 = (w & 7) * 16;
        const int d2 = tid & 127, rh = tid >> 7;   // 4 row-groups of 4
        float* wo_s = s;            // 64 x 128
        float* wv_s = s + 8192;     // 16 x 64
        float acc[4];
        #pragma unroll
        for (int j = 0; j < 4; j++) acc[j] = 0.f;
        for (int e0 = 0; e0 < 128; e0 += 64) {
            for (int i = tid; i < 8192; i += 512) {
                int e = i >> 7, dd = i & 127;
                wo_s[i] = Wo[(h * 128 + e0 + e) * DD + dd];
            }
            for (int i = tid; i < 1024; i += 512) {
                int r = i >> 6, e = i & 63;
                wv_s[i] = Wv[(r0 + r) * HE + h * 128 + e0 + e];
            }
            __syncthreads();
            #pragma unroll 8
            for (int e = 0; e < 64; e++) {
                float wo = wo_s[e * 128 + d2];
                #pragma unroll
                for (int j = 0; j < 4; j++)
                    acc[j] += wv_s[(rh * 4 + j) * 64 + e] * wo;
            }
            __syncthreads();
        }
        #pragma unroll
        for (int j = 0; j < 4; j++)
            g_M[(h * 128 + r0 + rh * 4 + j) * DD + d2] = acc[j];
    } else if (blk < 132) {
        // ---- cbias partial: k-slice of 256, 512 thr ----
        const int p = blk - 128, d2 = tid & 127, kh = tid >> 7;  // 4 k-groups
        float acc = 0.f;
        #pragma unroll 8
        for (int i = 0; i < 64; i++) {
            int k = p * 256 + kh * 64 + i;
            acc += __ldg(bv + k) * Wo[k * DD + d2];
        }
        s[tid] = acc;
        __syncthreads();
        if (kh == 0)
            g_cbp[p * DD + d2] = s[d2] + s[128 + d2] + s[256 + d2] + s[384 + d2]
                               + (p == 0 ? bo[d2] : 0.f);
    } else {
        // ---- S ----
        if (tid < 256) s[tid] = Ws[tid];
        __syncthreads();
        for (int st = 128; st > 0; st >>= 1) {
            if (tid < st) s[tid] += s[tid + st];
            __syncthreads();
        }
        if (tid == 0) g_S = s[0];
    }
}

// ===========================================================================
// K2: 2 CTAs per batch (cluster 2); rank r owns heads 4r..4r+3.
//   grid 128 x 1024 thr, ~160 KB dynamic smem, 1 CTA/SM.
//
// smem float offsets:
#define SX_PAD  132
#define OSX   0        // sx [256 t][132 d pad]   33792
#define OWS   33792    // Ws                      256
#define OXS   34048    // xs                      128
#define OSU   34176    // su [128 d][4 h] / sy    512
#define OSCO  34688    // scores [4 h][256 t]     1024
#define OBT   35712    // beta [256 t][4 h]       1024
#define OPART 36736    // scratch partials        4096
#define OSOUT 40832    // out partial (128 d2)    128
#define K2_FLOATS 40960

extern "C" __global__ __launch_bounds__(1024, 1) __cluster_dims__(2, 1, 1)
void k_main(const float* __restrict__ x, const float* __restrict__ Ws,
            float* __restrict__ out)
{
    extern __shared__ __align__(16) float sm[];
    float* sx    = sm + OSX;
    float* sWs   = sm + OWS;
    float* xs_f  = sm + OXS;
    float* su    = sm + OSU;     // later reused as sy
    float* sco   = sm + OSCO;
    float* sbeta = sm + OBT;
    float* spart = sm + OPART;
    float* sout  = sm + OSOUT;

    const int tid = threadIdx.x;
    uint32_t rank;
    asm("mov.u32 %0, %%cluster_ctarank;" : "=r"(rank));
    const int r = (int)rank;
    const uint32_t peer = 1u - rank;
    const int b = blockIdx.x >> 1;

    // ---- phase 0 (overlaps k_pre under PDL): full x tile + xs (redundant) ----
    if (tid < 256) sWs[tid] = Ws[tid];
    __syncthreads();
    {
        const int d = tid & 127, tg = tid >> 7;   // 8 t-groups of 32
        const float* xb = x + ((size_t)b * TT) * DD + d;
        float acc = 0.f;
        #pragma unroll
        for (int k = 0; k < 32; k++) {
            int t = k * 8 + tg;
            float v = xb[t * DD];
            sx[t * SX_PAD + d] = v;
            acc += sWs[t] * v;
        }
        spart[tg * 128 + d] = acc;
    }
    __syncthreads();
    if (tid < 128) {
        float v = 0.f;
        #pragma unroll
        for (int g = 0; g < 8; g++) v += spart[g * 128 + tid];
        xs_f[tid] = v;
    }
    __syncthreads();

    // first use of k_pre outputs — wait for its grid now
    cudaGridDependencySynchronize();
    const float S = g_S;

    // ---- phase 1: u for own 4 heads (float4 G loads) ----
    {   // h_l = tid>>8, strip = (tid>>5)&7 (8 x 16 dp), f4 = tid&31
        const int h_l = tid >> 8, strip = (tid >> 5) & 7, f4 = tid & 31;
        const int hg = 4 * r + h_l;
        const float4* G4 = (const float4*)g_G + hg * 4096 + f4;
        float4 acc = make_float4(0.f, 0.f, 0.f, 0.f);
        #pragma unroll
        for (int i = 0; i < 16; i++) {
            int dp = strip * 16 + i;
            float xv = xs_f[dp];
            float4 gv = G4[dp * 32];
            acc.x += xv * gv.x; acc.y += xv * gv.y;
            acc.z += xv * gv.z; acc.w += xv * gv.w;
        }
        ((float4*)spart)[strip * 128 + h_l * 32 + f4] = acc;
    }
    __syncthreads();
    if (tid < 512) {   // reduce 8 strips -> su[d*4 + h_l] (+ S*ub)
        const int h_l = tid >> 7, d = tid & 127;
        const int hg = 4 * r + h_l;
        const int o = h_l * 128 + d;
        float v = 0.f;
        #pragma unroll
        for (int s = 0; s < 8; s++) v += spart[s * 512 + o];
        su[d * 4 + h_l] = v + S * g_ub[hg * 128 + d];
    }
    __syncthreads();

    // ---- phase 2: summary for own 4 heads; thread (t = tid&255, dq = tid>>8) ----
    {
        const int t = tid & 255, dq = tid >> 8;   // 4 chunks of 32 d
        float xr[32];
        const float4* xrow = (const float4*)(sx + t * SX_PAD + dq * 32);
        #pragma unroll
        for (int i = 0; i < 8; i++) {
            float4 v = xrow[i];
            xr[i * 4 + 0] = v.x; xr[i * 4 + 1] = v.y;
            xr[i * 4 + 2] = v.z; xr[i * 4 + 3] = v.w;
        }
        unsigned long long a0 = 0, a1 = 0;
        #pragma unroll
        for (int i = 0; i < 32; i++) {
            int d = dq * 32 + i;
            unsigned long long xp = pk2(xr[i], xr[i]);
            ulonglong2 u4 = *(const ulonglong2*)(su + d * 4);
            ffma2(a0, u4.x, xp);
            ffma2(a1, u4.y, xp);
        }
        float2 f0 = upk2(a0), f1 = upk2(a1);
        float* pp = spart + dq * 1024 + t;
        pp[0]   = f0.x; pp[256] = f0.y;
        pp[512] = f1.x; pp[768] = f1.y;
    }
    __syncthreads();
    {   // reduce dq -> sco[h_l*256 + t]  (no c term: softmax shift-invariant)
        int h_l = tid >> 8, t = tid & 255;
        const float* pp = spart + h_l * 256 + t;
        sco[tid] = pp[0] + pp[1024] + pp[2048] + pp[3072];
    }
    __syncthreads();

    // ---- phase 3: full softmax over t (warp per own head), CTA-local ----
    if (tid < 128) {
        int h_l = tid >> 5, lane = tid & 31;
        float v[8];
        float m = -1e30f;
        #pragma unroll
        for (int i = 0; i < 8; i++) {
            v[i] = sco[h_l * 256 + lane + 32 * i];
            m = fmaxf(m, v[i]);
        }
        #pragma unroll
        for (int o = 16; o > 0; o >>= 1)
            m = fmaxf(m, __shfl_xor_sync(0xffffffffu, m, o));
        float ss = 0.f;
        #pragma unroll
        for (int i = 0; i < 8; i++) { v[i] = __expf(v[i] - m); ss += v[i]; }
        #pragma unroll
        for (int o = 16; o > 0; o >>= 1)
            ss += __shfl_xor_sync(0xffffffffu, ss, o);
        float inv = 1.f / ss;
        #pragma unroll
        for (int i = 0; i < 8; i++)
            sbeta[(lane + 32 * i) * 4 + h_l] = v[i] * inv;
    }
    __syncthreads();

    // ---- phase 4: y for own heads; thread (d = tid&127, tg = tid>>7 of 8) ----
    {
        const int d = tid & 127, tg = tid >> 7;
        unsigned long long a0 = 0, a1 = 0;
        #pragma unroll
        for (int i = 0; i < 32; i++) {
            int t = tg * 32 + i;
            float xv = sx[t * SX_PAD + d];
            unsigned long long xp = pk2(xv, xv);
            ulonglong2 b4 = *(const ulonglong2*)(sbeta + t * 4);
            ffma2(a0, b4.x, xp);
            ffma2(a1, b4.y, xp);
        }
        float2 v0 = upk2(a0), v1 = upk2(a1);
        float* pg = spart + tg * 512;
        pg[0 * 128 + d] = v0.x; pg[1 * 128 + d] = v0.y;
        pg[2 * 128 + d] = v1.x; pg[3 * 128 + d] = v1.y;
    }
    __syncthreads();
    if (tid < 512) {   // reduce 8 t-groups -> sy (reuse su); idx = h_l*128+d
        float v = 0.f;
        #pragma unroll
        for (int g = 0; g < 8; g++) v += spart[g * 512 + tid];
        su[tid] = v;
    }
    __syncthreads();

    // ---- phase 5: out partial over own 512 M rows (float4 M loads) ----
    {
        const int f4 = tid & 31, kg = tid >> 5;   // 32 groups of 16 k
        const float4* M4 = (const float4*)g_M + ((size_t)r * 512 + kg * 16) * 32 + f4;
        float4 acc = make_float4(0.f, 0.f, 0.f, 0.f);
        #pragma unroll
        for (int kk = 0; kk < 16; kk++) {
            float yk = su[kg * 16 + kk];
            float4 mv = M4[kk * 32];
            acc.x += yk * mv.x; acc.y += yk * mv.y;
            acc.z += yk * mv.z; acc.w += yk * mv.w;
        }
        ((float4*)spart)[kg * 32 + f4] = acc;
    }
    __syncthreads();
    if (tid < 128) {
        float v = 0.f;
        #pragma unroll
        for (int kg = 0; kg < 32; kg++) v += spart[kg * 128 + tid];
        sout[tid] = v;
    }
    CLUSTER_SYNC();   // #1: out partials visible cluster-wide
    if (tid < 64) {
        int d2 = r * 64 + tid;
        float o = 0.f;
        #pragma unroll
        for (int p = 0; p < 4; p++) o += g_cbp[p * DD + d2];
        o += sout[d2] + ld_dsmem(mapa_rank(smem_u32(sout + d2), peer));
        out[b * DD + d2] = o;
    }
    CLUSTER_SYNC();   // #2: exit guard
}

// ===========================================================================
extern "C" void kernel_launch(void* const* d_in, const int* in_sizes, int n_in,
                              void* d_out, int out_size) {
    const float* x  = (const float*)d_in[0];
    const float* Wq = (const float*)d_in[1];
    const float* bq = (const float*)d_in[2];   // unused (softmax shift-invariance)
    const float* Wk = (const float*)d_in[3];
    const float* bk = (const float*)d_in[4];
    const float* Wv = (const float*)d_in[5];
    const float* bv = (const float*)d_in[6];
    const float* Ws = (const float*)d_in[7];
    const float* bs = (const float*)d_in[8];   // unused (softmax shift-invariance)
    const float* Wo = (const float*)d_in[9];
    const float* bo = (const float*)d_in[10];
    float* out = (float*)d_out;
    (void)bq; (void)bs;

    static bool attr_done = false;
    if (!attr_done) {
        cudaFuncSetAttribute(k_main, cudaFuncAttributeMaxDynamicSharedMemorySize,
                             K2_FLOATS * 4);
        attr_done = true;
    }

    k_pre<<<133, 512>>>(Ws, Wk, bk, Wq, Wv, bv, Wo, bo);

    // k_main with PDL: k_pre triggers launch-completion at entry, so k_main's
    // phase 0 (x fill + xs) overlaps k_pre; gridDepSync gates first G/S use.
    cudaLaunchConfig_t cfg = {};
    cfg.gridDim = dim3(128, 1, 1);
    cfg.blockDim = dim3(1024, 1, 1);
    cfg.dynamicSmemBytes = K2_FLOATS * 4;
    cfg.stream = 0;
    cudaLaunchAttribute attrs[2];
    attrs[0].id = cudaLaunchAttributeProgrammaticStreamSerialization;
    attrs[0].val.programmaticStreamSerializationAllowed = 1;
    attrs[1].id = cudaLaunchAttributeClusterDimension;
    attrs[1].val.clusterDim = {2, 1, 1};
    cfg.attrs = attrs;
    cfg.numAttrs = 2;
    cudaLaunchKernelEx(&cfg, k_main, x, Ws, out);
}